// round 13
// baseline (speedup 1.0000x reference)
#include <cuda_runtime.h>
#include <cuda_bf16.h>
#include <math.h>
#include <stdint.h>

#define NN 30000
#define NE 480000
#define DDIM 128
#define EDIM 64
#define NH 8

// ---- scratch (__device__ globals; allocation is forbidden) ----
__device__ float g_Q[NN*DDIM], g_K[NN*DDIM], g_V[NN*DDIM];
__device__ float g_big[NE*DDIM];                 // Pe, later e-FFN mid
__device__ float g_sc[NE*NH], g_z[NN*NH];
__device__ float g_hattn[NN*DDIM];
__device__ float g_hb[NN*DDIM];
__device__ float g_hmid[NN*2*DDIM];
__device__ float g_eres[NE*EDIM], g_ebn[NE*EDIM];
__device__ float g_Wc[NH*EDIM], g_bc[EDIM];
__device__ float g_S[4][DDIM], g_Qs[4][DDIM], g_mean[4][DDIM], g_rstd[4][DDIM];
// stat slots: 0=BN1e 1=BN2e 2=BN1h 3=BN2h

__device__ __forceinline__ void mma16(float* d, const unsigned int* a,
                                      unsigned int b0, unsigned int b1) {
    asm("mma.sync.aligned.m16n8k16.row.col.f32.bf16.bf16.f32 "
        "{%0,%1,%2,%3},{%4,%5,%6,%7},{%8,%9},{%0,%1,%2,%3};"
        : "+f"(d[0]), "+f"(d[1]), "+f"(d[2]), "+f"(d[3])
        : "r"(a[0]), "r"(a[1]), "r"(a[2]), "r"(a[3]), "r"(b0), "r"(b1));
}

__device__ __forceinline__ void split2(float2 f, unsigned int& hi, unsigned int& lo) {
    __nv_bfloat162 h = __floats2bfloat162_rn(f.x, f.y);
    float2 hf = __bfloat1622float2(h);
    __nv_bfloat162 l2 = __floats2bfloat162_rn(f.x - hf.x, f.y - hf.y);
    hi = *reinterpret_cast<unsigned int*>(&h);
    lo = *reinterpret_cast<unsigned int*>(&l2);
}

__global__ void k_init() {
    int t = blockIdx.x*blockDim.x + threadIdx.x, st = gridDim.x*blockDim.x;
    for (int i = t; i < NN*DDIM; i += st) g_hattn[i] = 0.f;
    for (int i = t; i < NN*NH;  i += st) g_z[i] = 0.f;
    if (t < 4*DDIM) { (&g_S[0][0])[t] = 0.f; (&g_Qs[0][0])[t] = 0.f; }
}

__global__ void k_fold(const float* __restrict__ Wep, const float* __restrict__ bep,
                       const float* __restrict__ WOe, const float* __restrict__ bOe) {
    int t = threadIdx.x;                 // 512 threads
    int h = t >> 6, j = t & 63;
    float a = 0.f;
    for (int k = 0; k < EDIM; k++) a += Wep[h*EDIM + k] * WOe[k*EDIM + j];
    g_Wc[t] = a;
    if (t < EDIM) {
        float b = bOe[t];
        for (int k = 0; k < EDIM; k++) b += bep[k] * WOe[k*EDIM + t];
        g_bc[t] = b;
    }
}

// ---------------------------------------------------------------------------
// Pipelined split-bf16 tensor-core GEMM. 256 threads, strip = 128 rows.
// A is staged gmem -> regs -> smem (fragment-packed bf16 hi/lo), 2 stages,
// one __syncthreads per 32-k chunk. Warp w computes rows [w*16, w*16+16) of
// the strip across NTILE output cols (n0 = blockIdx.y*NTILE).
// ---------------------------------------------------------------------------
template<int DIN,int NTILE,bool RELU,bool INBN,bool EPIRES,bool RESBN>
__global__ void __launch_bounds__(256)
k_pgemm(const float* __restrict__ in, const float* __restrict__ W,
        const float* __restrict__ bias, float* __restrict__ out,
        int M, int WLD, int LD,
        const float* __restrict__ gaIn, const float* __restrict__ beIn, int slotIn,
        const float* __restrict__ resid, const float* __restrict__ gaR,
        const float* __restrict__ beR, int slotR)
{
    constexpr int NT  = NTILE/8;
    constexpr int KS  = DIN/16;          // total k16 steps
    constexpr int NCH = DIN/32;          // 32-k chunks per strip
    constexpr int WPF = KS*NT*128;       // packed W floats
    extern __shared__ float sm[];
    float* Wp = sm;                                    // [ks][t][lane] uint4
    unsigned int* Abuf = (unsigned int*)(sm + WPF);    // 8192 u32: 2stg x 2pl x 8wr x 2st x 32l x4
    float* scIn  = sm + WPF + 8192;                    // DIN
    float* shIn  = scIn + DIN;                         // DIN
    float* biasS = shIn + DIN;                         // NTILE
    float* scR   = biasS + NTILE;                      // NTILE
    float* shR   = scR + NTILE;                        // NTILE

    const int tid = threadIdx.x, l = tid & 31, w = tid >> 5;
    const int n0 = blockIdx.y * NTILE;

    // ---- stage W coalesced into Abuf, repack into Wp (bf16 hi/lo frag order) ----
    constexpr int RPP = 8192/NTILE;      // W rows per staging pass
    constexpr int NPASS = DIN/RPP;
    for (int ps = 0; ps < NPASS; ps++) {
        const int kr0 = ps*RPP;
        __syncthreads();
        for (int i = tid; i < RPP*NTILE/4; i += 256) {
            int kk = i/(NTILE/4), nn = (i%(NTILE/4))*4;
            ((float4*)Abuf)[i] = *(const float4*)(&W[(size_t)(kr0+kk)*WLD + n0 + nn]);
        }
        __syncthreads();
        const float* Wst = (const float*)Abuf;
        for (int i = tid; i < (RPP/16)*NT*32; i += 256) {
            int ll = i & 31, idx = i >> 5, t = idx % NT, sl = idx / NT;
            int klo = sl*16 + (ll&3)*2;
            int n = t*8 + (ll>>2);
            float2 w0 = make_float2(Wst[klo*NTILE + n],     Wst[(klo+1)*NTILE + n]);
            float2 w1 = make_float2(Wst[(klo+8)*NTILE + n], Wst[(klo+9)*NTILE + n]);
            unsigned int h0, lo0, h1, lo1;
            split2(w0, h0, lo0); split2(w1, h1, lo1);
            ((uint4*)Wp)[((kr0/16 + sl)*NT + t)*32 + ll] = make_uint4(h0, h1, lo0, lo1);
        }
    }
    for (int c = tid; c < NTILE; c += 256) biasS[c] = bias ? bias[n0+c] : 0.f;
    if (INBN)
        for (int c = tid; c < DIN; c += 256) {
            float s = gaIn[c]*g_rstd[slotIn][c];
            scIn[c] = s; shIn[c] = beIn[c] - g_mean[slotIn][c]*s;
        }
    if (RESBN)
        for (int c = tid; c < NTILE; c += 256) {
            float s = gaR[n0+c]*g_rstd[slotR][n0+c];
            scR[c] = s; shR[c] = beR[n0+c] - g_mean[slotR][n0+c]*s;
        }
    __syncthreads();

    const int nStrips = (M + 127) >> 7;
    int myStrips = (blockIdx.x < nStrips)
                 ? (nStrips - blockIdx.x + gridDim.x - 1) / gridDim.x : 0;
    const int nLocal = myStrips * NCH;
    if (nLocal == 0) return;

    float4 rb[2][4];
    auto loadChunk = [&](int p, float4* r4) {
        if (p >= nLocal) return;
        int q = p / NCH, ch = p % NCH;
        int strip = blockIdx.x + q*gridDim.x;
        int kb = ch*32;
#pragma unroll
        for (int j = 0; j < 4; j++) {
            int i4 = tid + j*256;                  // 0..1023
            int row = strip*128 + (i4 >> 3);
            if (row >= M) row = M - 1;
            int kq = (i4 & 7)*4;
            r4[j] = *(const float4*)(in + (size_t)row*DIN + kb + kq);
        }
    };
    auto storeChunk = [&](int p, float4* r4) {
        if (p >= nLocal) return;
        int ch = p % NCH, st = p & 1, kb = ch*32;
#pragma unroll
        for (int j = 0; j < 4; j++) {
            int i4 = tid + j*256;
            int row = i4 >> 3;                     // 0..127
            int kq = (i4 & 7)*4;
            float4 v = r4[j];
            if (INBN) {
                int c = kb + kq;
                v.x = v.x*scIn[c]   + shIn[c];   v.y = v.y*scIn[c+1] + shIn[c+1];
                v.z = v.z*scIn[c+2] + shIn[c+2]; v.w = v.w*scIn[c+3] + shIn[c+3];
            }
            unsigned int h0, lo0, h1, lo1;
            split2(make_float2(v.x, v.y), h0, lo0);
            split2(make_float2(v.z, v.w), h1, lo1);
            int kp0 = kq >> 1;                     // even kpair
            int wr = row >> 4, rr = row & 15;
            int step = kp0 >> 3;
            int comp = (rr >> 3) + (((kp0 >> 2) & 1) << 1);
            int lane0 = (row & 7)*4 + (kp0 & 3);
            int lane1 = (row & 7)*4 + ((kp0 + 1) & 3);
            unsigned int* A0 = Abuf + ((((st*2+0)*8 + wr)*2 + step)*32)*4;
            unsigned int* A1 = Abuf + ((((st*2+1)*8 + wr)*2 + step)*32)*4;
            A0[lane0*4 + comp] = h0;  A1[lane0*4 + comp] = lo0;
            A0[lane1*4 + comp] = h1;  A1[lane1*4 + comp] = lo1;
        }
    };

    float C[NT][4];
    loadChunk(0, rb[0]);
    storeChunk(0, rb[0]);
    loadChunk(1, rb[1]);

    for (int lp = 0; lp < nLocal; lp++) {
        const int q = lp / NCH, ch = lp % NCH;
        const int strip = blockIdx.x + q*gridDim.x;
        __syncthreads();                            // stage lp&1 ready, stage (lp+1)&1 free
        if (ch == 0) {
#pragma unroll
            for (int t = 0; t < NT; t++) {
                float b0 = biasS[t*8 + (l&3)*2], b1 = biasS[t*8 + (l&3)*2 + 1];
                C[t][0] = b0; C[t][1] = b1; C[t][2] = b0; C[t][3] = b1;
            }
        }
        {
            const int st = lp & 1;
#pragma unroll
            for (int s = 0; s < 2; s++) {
                uint4 ahi = ((uint4*)Abuf)[(((st*2+0)*8 + w)*2 + s)*32 + l];
                uint4 alo = ((uint4*)Abuf)[(((st*2+1)*8 + w)*2 + s)*32 + l];
                const int ks = ch*2 + s;
#pragma unroll
                for (int t = 0; t < NT; t++) {
                    uint4 pk = ((uint4*)Wp)[(ks*NT + t)*32 + l];
                    mma16(C[t], (unsigned int*)&ahi, pk.x, pk.y);
                    mma16(C[t], (unsigned int*)&ahi, pk.z, pk.w);
                    mma16(C[t], (unsigned int*)&alo, pk.x, pk.y);
                }
            }
        }
        storeChunk(lp+1, rb[(lp+1)&1]);
        loadChunk(lp+2, rb[lp&1]);
        if (ch == NCH-1) {
            const int rbase = strip*128 + w*16 + (l>>2);
#pragma unroll
            for (int t = 0; t < NT; t++) {
                const int col = n0 + t*8 + (l&3)*2;
#pragma unroll
                for (int hf = 0; hf < 2; hf++) {
                    int row = rbase + hf*8;
                    if (row < M) {
                        float v0 = C[t][hf*2], v1 = C[t][hf*2+1];
                        if (RELU) { v0 = fmaxf(v0, 0.f); v1 = fmaxf(v1, 0.f); }
                        if (EPIRES) {
                            float2 r2 = *(const float2*)(resid + (size_t)row*LD + col);
                            if (RESBN) {
                                r2.x = r2.x*scR[col-n0]   + shR[col-n0];
                                r2.y = r2.y*scR[col-n0+1] + shR[col-n0+1];
                            }
                            v0 += r2.x; v1 += r2.y;
                        }
                        *(float2*)(out + (size_t)row*LD + col) = make_float2(v0, v1);
                    }
                }
            }
        }
    }
}

template<int DIN,int NTILE,bool RELU,bool INBN,bool EPIRES,bool RESBN>
static void pgemm(dim3 grid, const float* in, const float* W, const float* bias,
                  float* out, int M, int WLD, int LD,
                  const float* gaIn = nullptr, const float* beIn = nullptr, int slotIn = 0,
                  const float* resid = nullptr, const float* gaR = nullptr,
                  const float* beR = nullptr, int slotR = 0)
{
    auto kfn = k_pgemm<DIN,NTILE,RELU,INBN,EPIRES,RESBN>;
    size_t sh = (size_t)((DIN/16)*(NTILE/8)*128 + 8192 + 2*DIN + 3*NTILE)*sizeof(float);
    cudaFuncSetAttribute(kfn, cudaFuncAttributeMaxDynamicSharedMemorySize, (int)sh);
    kfn<<<grid, 256, sh>>>(in, W, bias, out, M, WLD, LD, gaIn, beIn, slotIn,
                           resid, gaR, beR, slotR);
}

// per-channel sums over [M, C] -> g_S/g_Qs[slot]
template<int C>
__global__ void k_stats(const float* __restrict__ in, int slot, int M) {
    constexpr int SH = (C == 128) ? 7 : 6;
    int t = blockIdx.x*blockDim.x + threadIdx.x;
    int c = t & (C - 1);
    int r = t >> SH, rs = (gridDim.x*blockDim.x) >> SH;
    float s = 0.f, q = 0.f;
    for (; r < M; r += rs) {
        float v = in[(size_t)r*C + c];
        s += v; q += v*v;
    }
    atomicAdd(&g_S[slot][c], s); atomicAdd(&g_Qs[slot][c], q);
}

__global__ void k_score(const int* __restrict__ ei, const float* __restrict__ ea) {
    const int tid = threadIdx.x, l = tid & 31;
    int gw = (blockIdx.x*blockDim.x + tid) >> 5, tot = (gridDim.x*blockDim.x) >> 5;
    float2 w[NH];
#pragma unroll
    for (int h = 0; h < NH; h++) w[h] = ((const float2*)(g_Wc + h*EDIM))[l];
    float2 bc = ((const float2*)g_bc)[l];
    float s0 = 0.f, s1 = 0.f, q0 = 0.f, q1 = 0.f;
    for (int e = gw; e < NE; e += tot) {
        int s = ei[e], d = ei[NE + e];
        float4 q = ((const float4*)g_Q)[(size_t)d*32 + l];
        float4 k = ((const float4*)g_K)[(size_t)s*32 + l];
        float4 p = ((const float4*)g_big)[(size_t)e*32 + l];
        float sc = q.x*k.x*p.x + q.y*k.y*p.y + q.z*k.z*p.z + q.w*k.w*p.w;
        sc += __shfl_xor_sync(0xffffffffu, sc, 1);
        sc += __shfl_xor_sync(0xffffffffu, sc, 2);
        sc *= 0.25f;
        if ((l & 3) == 0) {
            float ex = __expf(fminf(fmaxf(sc, -5.f), 5.f));
            g_sc[(size_t)e*NH + (l >> 2)] = ex;
            atomicAdd(&g_z[(size_t)d*NH + (l >> 2)], ex);
        }
        float2 acc = bc;
#pragma unroll
        for (int h = 0; h < NH; h++) {
            float sv = __shfl_sync(0xffffffffu, sc, h*4);
            acc.x += sv*w[h].x; acc.y += sv*w[h].y;
        }
        float2 eav = ((const float2*)ea)[(size_t)e*32 + l];
        acc.x += eav.x; acc.y += eav.y;
        ((float2*)g_eres)[(size_t)e*32 + l] = acc;
        s0 += acc.x; q0 += acc.x*acc.x; s1 += acc.y; q1 += acc.y*acc.y;
    }
    atomicAdd(&g_S[0][2*l], s0);   atomicAdd(&g_S[0][2*l+1], s1);
    atomicAdd(&g_Qs[0][2*l], q0);  atomicAdd(&g_Qs[0][2*l+1], q1);
}

__global__ void k_alpha(const int* __restrict__ ei) {
    const int tid = threadIdx.x, l = tid & 31;
    int gw = (blockIdx.x*blockDim.x + tid) >> 5, tot = (gridDim.x*blockDim.x) >> 5;
    for (int e = gw; e < NE; e += tot) {
        int s = ei[e], d = ei[NE + e];
        int h = l >> 2;
        float a = g_sc[(size_t)e*NH + h] / (g_z[(size_t)d*NH + h] + 1e-6f);
        float4 v = ((const float4*)g_V)[(size_t)s*32 + l];
        atomicAdd(((float4*)(g_hattn + (size_t)d*DDIM)) + l,
                  make_float4(v.x*a, v.y*a, v.z*a, v.w*a));
    }
}

__global__ void k_bnfin(int slot, int C, float invn) {
    int i = threadIdx.x;
    if (i < C) {
        float mu = g_S[slot][i] * invn;
        float var = g_Qs[slot][i] * invn - mu*mu;
        g_mean[slot][i] = mu;
        g_rstd[slot][i] = rsqrtf(var + 1e-5f);
    }
}

template<int C>
__global__ void k_bnapply(const float* __restrict__ in, float* __restrict__ out,
                          const float* __restrict__ ga, const float* __restrict__ be,
                          int slot, size_t total) {
    size_t i0 = (size_t)blockIdx.x*blockDim.x + threadIdx.x;
    size_t st = (size_t)gridDim.x*blockDim.x;
    int c = (int)(i0 & (C - 1));
    float sc = ga[c] * g_rstd[slot][c];
    float sh = be[c] - g_mean[slot][c] * sc;
    for (size_t i = i0; i < total; i += st) out[i] = in[i]*sc + sh;
}

extern "C" void kernel_launch(void* const* d_in, const int* in_sizes, int n_in,
                              void* d_out, int out_size) {
    const float* x   = (const float*)d_in[0];
    const int*   ei  = (const int*)  d_in[1];
    const float* ea  = (const float*)d_in[2];
    const float *Wq = (const float*)d_in[3], *Wk = (const float*)d_in[4];
    const float *Wv = (const float*)d_in[5], *We = (const float*)d_in[6];
    const float *WOh = (const float*)d_in[7],  *bOh = (const float*)d_in[8];
    const float *Wep = (const float*)d_in[9],  *bep = (const float*)d_in[10];
    const float *WOe = (const float*)d_in[11], *bOe = (const float*)d_in[12];
    const float *Wh1 = (const float*)d_in[13], *bh1 = (const float*)d_in[14];
    const float *Wh2 = (const float*)d_in[15], *bh2 = (const float*)d_in[16];
    const float *We1 = (const float*)d_in[17], *be1 = (const float*)d_in[18];
    const float *We2 = (const float*)d_in[19], *be2 = (const float*)d_in[20];
    const float *g1h = (const float*)d_in[21], *B1h = (const float*)d_in[22];
    const float *g1e = (const float*)d_in[23], *B1e = (const float*)d_in[24];
    const float *g2h = (const float*)d_in[25], *B2h = (const float*)d_in[26];
    const float *g2e = (const float*)d_in[27], *B2e = (const float*)d_in[28];
    float* out_h = (float*)d_out;
    float* out_e = out_h + (size_t)NN*DDIM;

    float *pQ, *pK, *pV, *pBig, *pHat, *pHb, *pHmid, *pEres, *pEbn;
    cudaGetSymbolAddress((void**)&pQ, g_Q);
    cudaGetSymbolAddress((void**)&pK, g_K);
    cudaGetSymbolAddress((void**)&pV, g_V);
    cudaGetSymbolAddress((void**)&pBig, g_big);
    cudaGetSymbolAddress((void**)&pHat, g_hattn);
    cudaGetSymbolAddress((void**)&pHb, g_hb);
    cudaGetSymbolAddress((void**)&pHmid, g_hmid);
    cudaGetSymbolAddress((void**)&pEres, g_eres);
    cudaGetSymbolAddress((void**)&pEbn, g_ebn);

    k_init<<<592, 256>>>();
    k_fold<<<1, 512>>>(Wep, bep, WOe, bOe);

    // attention projections
    pgemm<128,128,false,false,false,false>(dim3(235,1), x, Wq, nullptr, pQ, NN, 128, 128);
    pgemm<128,128,false,false,false,false>(dim3(235,1), x, Wk, nullptr, pK, NN, 128, 128);
    pgemm<128,128,false,false,false,false>(dim3(235,1), x, Wv, nullptr, pV, NN, 128, 128);
    pgemm< 64,128,false,false,false,false>(dim3(296,1), ea, We, nullptr, pBig, NE, 128, 128);

    // score + softmax denom + fused e_lin/residual/BN1e stats
    k_score<<<592, 256>>>(ei, ea);
    k_bnfin<<<1, 128>>>(0, EDIM, 1.f/NE);
    k_alpha<<<592, 256>>>(ei);

    // h path
    pgemm<128,128,false,false,true,false>(dim3(235,1), pHat, WOh, bOh, pHb, NN, 128, 128,
        nullptr, nullptr, 0, x);
    k_stats<128><<<592, 256>>>(pHb, 2, NN);
    k_bnfin<<<1, 128>>>(2, DDIM, 1.f/NN);
    pgemm<128,128,true,true,false,false>(dim3(235,2), pHb, Wh1, bh1, pHmid, NN, 256, 256,
        g1h, B1h, 2);
    pgemm<256,128,false,false,true,true>(dim3(235,1), pHmid, Wh2, bh2, pQ, NN, 128, 128,
        nullptr, nullptr, 0, pHb, g1h, B1h, 2);
    k_stats<128><<<592, 256>>>(pQ, 3, NN);
    k_bnfin<<<1, 128>>>(3, DDIM, 1.f/NN);
    k_bnapply<128><<<592, 256>>>(pQ, out_h, g2h, B2h, 3, (size_t)NN*DDIM);

    // e path
    pgemm< 64,128,true,true,false,false>(dim3(296,1), pEres, We1, be1, pBig, NE, 128, 128,
        g1e, B1e, 0);
    pgemm<128, 64,false,false,true,true>(dim3(296,1), pBig, We2, be2, pEbn, NE, 64, 64,
        nullptr, nullptr, 0, pEres, g1e, B1e, 0);
    k_stats<64><<<1024, 256>>>(pEbn, 1, NE);
    k_bnfin<<<1, 128>>>(1, EDIM, 1.f/NE);
    k_bnapply<64><<<592, 256>>>(pEbn, out_e, g2e, B2e, 1, (size_t)NE*EDIM);
}

// round 14
// speedup vs baseline: 1.0507x; 1.0507x over previous
#include <cuda_runtime.h>
#include <cuda_bf16.h>
#include <math.h>
#include <stdint.h>

#define NN 30000
#define NE 480000
#define DDIM 128
#define EDIM 64
#define NH 8

// ---- scratch (__device__ globals; allocation is forbidden) ----
__device__ float g_Q[NN*DDIM], g_K[NN*DDIM], g_V[NN*DDIM];
__device__ float g_big[NE*DDIM];                 // Pe, later e-FFN mid
__device__ float g_sc[NE*NH], g_z[NN*NH];
__device__ float g_hattn[NN*DDIM];
__device__ float g_hb[NN*DDIM];
__device__ float g_hmid[NN*2*DDIM];
__device__ float g_eres[NE*EDIM], g_ebn[NE*EDIM];
__device__ float g_Wc[NH*EDIM], g_bc[EDIM];
__device__ float g_S[4][DDIM], g_Qs[4][DDIM], g_mean[4][DDIM], g_rstd[4][DDIM];
// stat slots: 0=BN1e 1=BN2e 2=BN1h 3=BN2h

__device__ __forceinline__ void mma16(float* d, const unsigned int* a,
                                      unsigned int b0, unsigned int b1) {
    asm("mma.sync.aligned.m16n8k16.row.col.f32.bf16.bf16.f32 "
        "{%0,%1,%2,%3},{%4,%5,%6,%7},{%8,%9},{%0,%1,%2,%3};"
        : "+f"(d[0]), "+f"(d[1]), "+f"(d[2]), "+f"(d[3])
        : "r"(a[0]), "r"(a[1]), "r"(a[2]), "r"(a[3]), "r"(b0), "r"(b1));
}

// split a float2 into packed bf16x2 hi and lo (a = hi + lo + O(2^-17 a))
__device__ __forceinline__ void split2(float2 f, unsigned int& hi, unsigned int& lo) {
    __nv_bfloat162 h = __floats2bfloat162_rn(f.x, f.y);
    float2 hf = __bfloat1622float2(h);
    __nv_bfloat162 l2 = __floats2bfloat162_rn(f.x - hf.x, f.y - hf.y);
    hi = *reinterpret_cast<unsigned int*>(&h);
    lo = *reinterpret_cast<unsigned int*>(&l2);
}

__global__ void k_init() {
    int t = blockIdx.x*blockDim.x + threadIdx.x, st = gridDim.x*blockDim.x;
    for (int i = t; i < NN*DDIM; i += st) g_hattn[i] = 0.f;
    for (int i = t; i < NN*NH;  i += st) g_z[i] = 0.f;
    if (t < 4*DDIM) { (&g_S[0][0])[t] = 0.f; (&g_Qs[0][0])[t] = 0.f; }
}

// fold Wc = W_ep @ W_Oe, bc = b_ep @ W_Oe + b_Oe
__global__ void k_fold(const float* __restrict__ Wep, const float* __restrict__ bep,
                       const float* __restrict__ WOe, const float* __restrict__ bOe) {
    int t = threadIdx.x;                 // 512 threads
    int h = t >> 6, j = t & 63;
    float a = 0.f;
    for (int k = 0; k < EDIM; k++) a += Wep[h*EDIM + k] * WOe[k*EDIM + j];
    g_Wc[t] = a;
    if (t < EDIM) {
        float b = bOe[t];
        for (int k = 0; k < EDIM; k++) b += bep[k] * WOe[k*EDIM + t];
        g_bc[t] = b;
    }
}

// ---------------------------------------------------------------------------
// Tensor-core GEMM: split-bf16 (hi/lo) 3-term compensation on mma.m16n8k16.
// Round-12 structure, but stats moved out and __launch_bounds__(256,3) for
// 3 CTAs/SM. Warp computes 16 x NT*8 tile; A prefetched 1 step ahead.
// ---------------------------------------------------------------------------
template<int DIN,int NT,bool RELU,bool INBN,bool EPIRES,bool RESBN>
__global__ void __launch_bounds__(256, 3)
k_tgemm(const float* __restrict__ in, const float* __restrict__ W,
        const float* __restrict__ bias, float* __restrict__ out,
        int M, int WLD, int LD,
        const float* __restrict__ gaIn, const float* __restrict__ beIn, int slotIn,
        const float* __restrict__ resid, const float* __restrict__ gaR,
        const float* __restrict__ beR, int slotR)
{
    constexpr int NW = 8;                  // 256 threads
    constexpr int KS = DIN/16;             // k16 steps
    extern __shared__ float sm[];
    float* Wp    = sm;                     // NT*KS*128 words: uint4/lane {hi0,hi1,lo0,lo1}
    float* scIn  = Wp + NT*KS*128;         // DIN
    float* shIn  = scIn + DIN;             // DIN
    float* biasS = shIn + DIN;             // NT*8
    float* scR   = biasS + NT*8;           // NT*8
    float* shR   = scR + NT*8;             // NT*8
    const int tid = threadIdx.x, l = tid & 31, wid = tid >> 5;
    const int n0 = blockIdx.y * NT * 8;

    // pack W tile: lane covers n = n0+t*8+(l>>2), k pairs (k0,k0+1) and (k0+8,k0+9)
    for (int i = tid; i < NT*KS*32; i += 256) {
        int ll = i & 31, si = (i >> 5) % KS, ti = (i >> 5) / KS;
        int k0 = si*16 + (ll & 3)*2, n = n0 + ti*8 + (ll >> 2);
        float2 w0 = make_float2(W[(size_t)k0*WLD + n],     W[(size_t)(k0+1)*WLD + n]);
        float2 w1 = make_float2(W[(size_t)(k0+8)*WLD + n], W[(size_t)(k0+9)*WLD + n]);
        unsigned int h0, l0, h1, l1;
        split2(w0, h0, l0); split2(w1, h1, l1);
        ((uint4*)Wp)[i] = make_uint4(h0, h1, l0, l1);
    }
    for (int c = tid; c < NT*8; c += 256) biasS[c] = bias ? bias[n0 + c] : 0.f;
    if (INBN)
        for (int c = tid; c < DIN; c += 256) {
            float s = gaIn[c] * g_rstd[slotIn][c];
            scIn[c] = s; shIn[c] = beIn[c] - g_mean[slotIn][c]*s;
        }
    if (RESBN)
        for (int c = tid; c < NT*8; c += 256) {
            float s = gaR[n0+c] * g_rstd[slotR][n0+c];
            scR[c] = s; shR[c] = beR[n0+c] - g_mean[slotR][n0+c]*s;
        }
    __syncthreads();

    const int nstrip = M / 16;
    for (int strip = blockIdx.x*NW + wid; strip < nstrip; strip += gridDim.x*NW) {
        const int r0 = strip * 16;
        float C[NT][4];
#pragma unroll
        for (int t = 0; t < NT; t++) {
            float b0 = biasS[t*8 + (l&3)*2], b1 = biasS[t*8 + (l&3)*2 + 1];
            C[t][0] = b0; C[t][1] = b1; C[t][2] = b0; C[t][3] = b1;
        }
        const float* aBase = in + (size_t)(r0 + (l>>2))*DIN + (l&3)*2;
        // per step: raw = {(r,k0) , (r+8,k0) , (r,k0+8) , (r+8,k0+8)}
#define LOADA(S, DST)                                                      \
        {                                                                  \
            const float* p = aBase + (S)*16;                               \
            DST[0] = *(const float2*)(p);                                  \
            DST[1] = *(const float2*)(p + (size_t)8*DIN);                  \
            DST[2] = *(const float2*)(p + 8);                              \
            DST[3] = *(const float2*)(p + (size_t)8*DIN + 8);              \
        }
        float2 raw[4], rawN[4];
        LOADA(0, raw);
#pragma unroll 1
        for (int s = 0; s < KS; s++) {
            if (s + 1 < KS) LOADA(s+1, rawN);
            float2 sc0, sh0, sc1, sh1;
            if (INBN) {
                int c0 = s*16 + (l&3)*2;
                sc0 = *(float2*)(scIn + c0);     sh0 = *(float2*)(shIn + c0);
                sc1 = *(float2*)(scIn + c0 + 8); sh1 = *(float2*)(shIn + c0 + 8);
            }
            unsigned int ahi[4], alo[4];
#pragma unroll
            for (int j = 0; j < 4; j++) {
                float2 a = raw[j];
                if (INBN) {
                    float2 s2 = (j >> 1) ? sc1 : sc0, h2 = (j >> 1) ? sh1 : sh0;
                    a.x = a.x*s2.x + h2.x; a.y = a.y*s2.y + h2.y;
                }
                split2(a, ahi[j], alo[j]);
            }
#pragma unroll
            for (int t = 0; t < NT; t++) {
                uint4 pk = ((const uint4*)Wp)[(t*KS + s)*32 + l];
                mma16(C[t], ahi, pk.x, pk.y);
                mma16(C[t], ahi, pk.z, pk.w);
                mma16(C[t], alo, pk.x, pk.y);
            }
#pragma unroll
            for (int j = 0; j < 4; j++) raw[j] = rawN[j];
        }
#undef LOADA
        // epilogue
#pragma unroll
        for (int t = 0; t < NT; t++) {
            const int col = n0 + t*8 + (l&3)*2;
#pragma unroll
            for (int half = 0; half < 2; half++) {
                int row = r0 + (l>>2) + half*8;
                float v0 = C[t][half*2], v1 = C[t][half*2 + 1];
                if (RELU) { v0 = fmaxf(v0, 0.f); v1 = fmaxf(v1, 0.f); }
                if (EPIRES) {
                    float2 r2 = *(const float2*)(resid + (size_t)row*LD + col);
                    if (RESBN) {
                        r2.x = r2.x*scR[t*8+(l&3)*2]   + shR[t*8+(l&3)*2];
                        r2.y = r2.y*scR[t*8+(l&3)*2+1] + shR[t*8+(l&3)*2+1];
                    }
                    v0 += r2.x; v1 += r2.y;
                }
                *(float2*)(out + (size_t)row*LD + col) = make_float2(v0, v1);
            }
        }
    }
}

template<int DIN,int NT,bool RELU,bool INBN,bool EPIRES,bool RESBN>
static void tgemm(dim3 grid, const float* in, const float* W, const float* bias,
                  float* out, int M, int WLD, int LD,
                  const float* gaIn = nullptr, const float* beIn = nullptr, int slotIn = 0,
                  const float* resid = nullptr, const float* gaR = nullptr,
                  const float* beR = nullptr, int slotR = 0)
{
    auto kfn = k_tgemm<DIN,NT,RELU,INBN,EPIRES,RESBN>;
    size_t sh = (size_t)(NT*(DIN/16)*128 + 2*DIN + 3*NT*8) * sizeof(float);
    cudaFuncSetAttribute(kfn, cudaFuncAttributeMaxDynamicSharedMemorySize, (int)sh);
    kfn<<<grid, 256, sh>>>(in, W, bias, out, M, WLD, LD, gaIn, beIn, slotIn,
                           resid, gaR, beR, slotR);
}

// per-channel sums over [M, C] -> g_S/g_Qs[slot]
template<int C>
__global__ void k_stats(const float* __restrict__ in, int slot, int M) {
    constexpr int SH = (C == 128) ? 7 : 6;
    int t = blockIdx.x*blockDim.x + threadIdx.x;
    int c = t & (C - 1);
    int r = t >> SH, rs = (gridDim.x*blockDim.x) >> SH;
    float s = 0.f, q = 0.f;
    for (; r < M; r += rs) {
        float v = in[(size_t)r*C + c];
        s += v; q += v*v;
    }
    atomicAdd(&g_S[slot][c], s); atomicAdd(&g_Qs[slot][c], q);
}

// per-edge: score, exp+clip, z scatter, and fused e_lin + residual + BN1e stats
__global__ void k_score(const int* __restrict__ ei, const float* __restrict__ ea) {
    const int tid = threadIdx.x, l = tid & 31;
    int gw = (blockIdx.x*blockDim.x + tid) >> 5, tot = (gridDim.x*blockDim.x) >> 5;
    float2 w[NH];
#pragma unroll
    for (int h = 0; h < NH; h++) w[h] = ((const float2*)(g_Wc + h*EDIM))[l];
    float2 bc = ((const float2*)g_bc)[l];
    float s0 = 0.f, s1 = 0.f, q0 = 0.f, q1 = 0.f;
    for (int e = gw; e < NE; e += tot) {
        int s = ei[e], d = ei[NE + e];
        float4 q = ((const float4*)g_Q)[(size_t)d*32 + l];
        float4 k = ((const float4*)g_K)[(size_t)s*32 + l];
        float4 p = ((const float4*)g_big)[(size_t)e*32 + l];
        float sc = q.x*k.x*p.x + q.y*k.y*p.y + q.z*k.z*p.z + q.w*k.w*p.w;
        sc += __shfl_xor_sync(0xffffffffu, sc, 1);
        sc += __shfl_xor_sync(0xffffffffu, sc, 2);
        sc *= 0.25f;                                   // 1/sqrt(16)
        if ((l & 3) == 0) {
            float ex = __expf(fminf(fmaxf(sc, -5.f), 5.f));
            g_sc[(size_t)e*NH + (l >> 2)] = ex;
            atomicAdd(&g_z[(size_t)d*NH + (l >> 2)], ex);
        }
        float2 acc = bc;
#pragma unroll
        for (int h = 0; h < NH; h++) {
            float sv = __shfl_sync(0xffffffffu, sc, h*4);
            acc.x += sv*w[h].x; acc.y += sv*w[h].y;
        }
        float2 eav = ((const float2*)ea)[(size_t)e*32 + l];
        acc.x += eav.x; acc.y += eav.y;
        ((float2*)g_eres)[(size_t)e*32 + l] = acc;
        s0 += acc.x; q0 += acc.x*acc.x; s1 += acc.y; q1 += acc.y*acc.y;
    }
    atomicAdd(&g_S[0][2*l], s0);   atomicAdd(&g_S[0][2*l+1], s1);
    atomicAdd(&g_Qs[0][2*l], q0);  atomicAdd(&g_Qs[0][2*l+1], q1);
}

// per-edge: alpha = sc/(z+eps); hattn[dst] += V[src]*alpha  (vector RED)
__global__ void k_alpha(const int* __restrict__ ei) {
    const int tid = threadIdx.x, l = tid & 31;
    int gw = (blockIdx.x*blockDim.x + tid) >> 5, tot = (gridDim.x*blockDim.x) >> 5;
    for (int e = gw; e < NE; e += tot) {
        int s = ei[e], d = ei[NE + e];
        int h = l >> 2;
        float a = g_sc[(size_t)e*NH + h] / (g_z[(size_t)d*NH + h] + 1e-6f);
        float4 v = ((const float4*)g_V)[(size_t)s*32 + l];
        atomicAdd(((float4*)(g_hattn + (size_t)d*DDIM)) + l,
                  make_float4(v.x*a, v.y*a, v.z*a, v.w*a));
    }
}

__global__ void k_bnfin(int slot, int C, float invn) {
    int i = threadIdx.x;
    if (i < C) {
        float mu = g_S[slot][i] * invn;
        float var = g_Qs[slot][i] * invn - mu*mu;
        g_mean[slot][i] = mu;
        g_rstd[slot][i] = rsqrtf(var + 1e-5f);
    }
}

template<int C>
__global__ void k_bnapply(const float* __restrict__ in, float* __restrict__ out,
                          const float* __restrict__ ga, const float* __restrict__ be,
                          int slot, size_t total) {
    size_t i0 = (size_t)blockIdx.x*blockDim.x + threadIdx.x;
    size_t st = (size_t)gridDim.x*blockDim.x;
    int c = (int)(i0 & (C - 1));
    float sc = ga[c] * g_rstd[slot][c];
    float sh = be[c] - g_mean[slot][c] * sc;
    for (size_t i = i0; i < total; i += st) out[i] = in[i]*sc + sh;
}

extern "C" void kernel_launch(void* const* d_in, const int* in_sizes, int n_in,
                              void* d_out, int out_size) {
    const float* x   = (const float*)d_in[0];
    const int*   ei  = (const int*)  d_in[1];
    const float* ea  = (const float*)d_in[2];
    const float *Wq = (const float*)d_in[3], *Wk = (const float*)d_in[4];
    const float *Wv = (const float*)d_in[5], *We = (const float*)d_in[6];
    const float *WOh = (const float*)d_in[7],  *bOh = (const float*)d_in[8];
    const float *Wep = (const float*)d_in[9],  *bep = (const float*)d_in[10];
    const float *WOe = (const float*)d_in[11], *bOe = (const float*)d_in[12];
    const float *Wh1 = (const float*)d_in[13], *bh1 = (const float*)d_in[14];
    const float *Wh2 = (const float*)d_in[15], *bh2 = (const float*)d_in[16];
    const float *We1 = (const float*)d_in[17], *be1 = (const float*)d_in[18];
    const float *We2 = (const float*)d_in[19], *be2 = (const float*)d_in[20];
    const float *g1h = (const float*)d_in[21], *B1h = (const float*)d_in[22];
    const float *g1e = (const float*)d_in[23], *B1e = (const float*)d_in[24];
    const float *g2h = (const float*)d_in[25], *B2h = (const float*)d_in[26];
    const float *g2e = (const float*)d_in[27], *B2e = (const float*)d_in[28];
    float* out_h = (float*)d_out;
    float* out_e = out_h + (size_t)NN*DDIM;

    float *pQ, *pK, *pV, *pBig, *pHat, *pHb, *pHmid, *pEres, *pEbn;
    cudaGetSymbolAddress((void**)&pQ, g_Q);
    cudaGetSymbolAddress((void**)&pK, g_K);
    cudaGetSymbolAddress((void**)&pV, g_V);
    cudaGetSymbolAddress((void**)&pBig, g_big);
    cudaGetSymbolAddress((void**)&pHat, g_hattn);
    cudaGetSymbolAddress((void**)&pHb, g_hb);
    cudaGetSymbolAddress((void**)&pHmid, g_hmid);
    cudaGetSymbolAddress((void**)&pEres, g_eres);
    cudaGetSymbolAddress((void**)&pEbn, g_ebn);

    k_init<<<592, 256>>>();
    k_fold<<<1, 512>>>(Wep, bep, WOe, bOe);

    // attention projections (tensor core, split-bf16)
    tgemm<128,8,false,false,false,false>(dim3(235,2), x, Wq, nullptr, pQ, NN, 128, 128);
    tgemm<128,8,false,false,false,false>(dim3(235,2), x, Wk, nullptr, pK, NN, 128, 128);
    tgemm<128,8,false,false,false,false>(dim3(235,2), x, Wv, nullptr, pV, NN, 128, 128);
    tgemm< 64,8,false,false,false,false>(dim3(296,2), ea, We, nullptr, pBig, NE, 128, 128); // Pe

    // score + softmax denom + fused e_lin/residual/BN1e stats
    k_score<<<592, 256>>>(ei, ea);
    k_bnfin<<<1, 128>>>(0, EDIM, 1.f/NE);
    k_alpha<<<592, 256>>>(ei);

    // h path: Oh proj + residual(x)
    tgemm<128,8,false,false,true,false>(dim3(235,2), pHat, WOh, bOh, pHb, NN, 128, 128,
        nullptr, nullptr, 0, x);
    k_stats<128><<<592, 256>>>(pHb, 2, NN);
    k_bnfin<<<1, 128>>>(2, DDIM, 1.f/NN);
    // FFN1: BN1h applied inline on input rows
    tgemm<128,8,true,true,false,false>(dim3(235,4), pHb, Wh1, bh1, pHmid, NN, 256, 256,
        g1h, B1h, 2);
    // FFN2: residual = BN1h(hb) recomputed inline
    tgemm<256,8,false,false,true,true>(dim3(235,2), pHmid, Wh2, bh2, pQ, NN, 128, 128,
        nullptr, nullptr, 0, pHb, g1h, B1h, 2);
    k_stats<128><<<592, 256>>>(pQ, 3, NN);
    k_bnfin<<<1, 128>>>(3, DDIM, 1.f/NN);
    k_bnapply<128><<<592, 256>>>(pQ, out_h, g2h, B2h, 3, (size_t)NN*DDIM);

    // e path: FFN1 with BN1e inline on eres
    tgemm< 64,8,true,true,false,false>(dim3(296,2), pEres, We1, be1, pBig, NE, 128, 128,
        g1e, B1e, 0);
    // FFN2: residual = BN1e(eres) inline
    tgemm<128,8,false,false,true,true>(dim3(592,1), pBig, We2, be2, pEbn, NE, 64, 64,
        nullptr, nullptr, 0, pEres, g1e, B1e, 0);
    k_stats<64><<<1024, 256>>>(pEbn, 1, NE);
    k_bnfin<<<1, 128>>>(1, EDIM, 1.f/NE);
    k_bnapply<64><<<592, 256>>>(pEbn, out_e, g2e, B2e, 1, (size_t)NE*EDIM);
}